// round 3
// baseline (speedup 1.0000x reference)
#include <cuda_runtime.h>
#include <cstdint>

typedef unsigned long long u64;
typedef unsigned int u32;

#define B_ROWS 2048
#define N_TRAIN 100000
#define KDIM 1024
#define NCLS 1000
#define MAXK 200
#define CAP 4096
#define TINV (1.0f / 0.07f)

// 800 MB scratch for the similarity matrix (device global: allocation-free).
__device__ float g_sim[(size_t)B_ROWS * N_TRAIN];

// ---------------------------------------------------------------------------
// Packed f32x2 helpers (Blackwell): 2 fp32 MACs per instruction.
// ---------------------------------------------------------------------------
__device__ __forceinline__ u64 ffma2(u64 a, u64 b, u64 c) {
    u64 d;
    asm("fma.rn.f32x2 %0, %1, %2, %3;" : "=l"(d) : "l"(a), "l"(b), "l"(c));
    return d;
}
__device__ __forceinline__ u64 packf2(float lo, float hi) {
    u64 r;
    asm("mov.b64 %0, {%1, %2};" : "=l"(r) : "f"(lo), "f"(hi));
    return r;
}

// ---------------------------------------------------------------------------
// GEMM: sim[m][n] = sum_d A[m][d] * B[n][d]   (both K-contiguous, "NT")
// 128x128 tile, BK=16, 256 threads, 8x8 per thread, f32x2-packed along n.
// ---------------------------------------------------------------------------
#define BM 128
#define BN 128
#define BK 16
#define TSTRIDE 132   // padded smem row stride (floats), 16B-divisible

__global__ __launch_bounds__(256, 2) void gemm_kernel(
    const float* __restrict__ A, const float* __restrict__ B)
{
    __shared__ float As[BK][TSTRIDE];
    __shared__ float Bs[BK][TSTRIDE];

    const int tid = threadIdx.x;
    const int m_base = blockIdx.y * BM;
    const int n_base = blockIdx.x * BN;

    // tile-load mapping: 128 rows x 16 cols = 512 float4; 2 float4 / thread
    const int lrow = tid >> 2;          // 0..63
    const int lcol = (tid & 3) << 2;    // 0,4,8,12

    // compute mapping: 16x16 thread grid, 8x8 outputs each
    const int ty = tid >> 4, tx = tid & 15;
    const int m0 = ty * 8, n0 = tx * 8;

    u64 acc[8][4];
#pragma unroll
    for (int i = 0; i < 8; i++)
#pragma unroll
        for (int j = 0; j < 4; j++) acc[i][j] = 0ULL;

    const int mA0 = m_base + lrow;      // always < 2048
    const int mA1 = mA0 + 64;
    const int nB0 = n_base + lrow;      // may exceed N_TRAIN on last tile
    const int nB1 = nB0 + 64;

    for (int kt = 0; kt < KDIM; kt += BK) {
        float4 a0 = *(const float4*)(A + (size_t)mA0 * KDIM + kt + lcol);
        float4 a1 = *(const float4*)(A + (size_t)mA1 * KDIM + kt + lcol);
        float4 b0 = make_float4(0.f, 0.f, 0.f, 0.f);
        float4 b1 = make_float4(0.f, 0.f, 0.f, 0.f);
        if (nB0 < N_TRAIN) b0 = *(const float4*)(B + (size_t)nB0 * KDIM + kt + lcol);
        if (nB1 < N_TRAIN) b1 = *(const float4*)(B + (size_t)nB1 * KDIM + kt + lcol);

        __syncthreads();   // previous tile's compute done before overwrite
        As[lcol + 0][lrow] = a0.x; As[lcol + 1][lrow] = a0.y;
        As[lcol + 2][lrow] = a0.z; As[lcol + 3][lrow] = a0.w;
        As[lcol + 0][lrow + 64] = a1.x; As[lcol + 1][lrow + 64] = a1.y;
        As[lcol + 2][lrow + 64] = a1.z; As[lcol + 3][lrow + 64] = a1.w;
        Bs[lcol + 0][lrow] = b0.x; Bs[lcol + 1][lrow] = b0.y;
        Bs[lcol + 2][lrow] = b0.z; Bs[lcol + 3][lrow] = b0.w;
        Bs[lcol + 0][lrow + 64] = b1.x; Bs[lcol + 1][lrow + 64] = b1.y;
        Bs[lcol + 2][lrow + 64] = b1.z; Bs[lcol + 3][lrow + 64] = b1.w;
        __syncthreads();

#pragma unroll
        for (int k = 0; k < BK; k++) {
            float4 av0 = *(const float4*)&As[k][m0];
            float4 av1 = *(const float4*)&As[k][m0 + 4];
            float4 bv0 = *(const float4*)&Bs[k][n0];
            float4 bv1 = *(const float4*)&Bs[k][n0 + 4];
            u64 b2[4];
            b2[0] = packf2(bv0.x, bv0.y);
            b2[1] = packf2(bv0.z, bv0.w);
            b2[2] = packf2(bv1.x, bv1.y);
            b2[3] = packf2(bv1.z, bv1.w);
            float a[8] = {av0.x, av0.y, av0.z, av0.w, av1.x, av1.y, av1.z, av1.w};
#pragma unroll
            for (int i = 0; i < 8; i++) {
                u64 a2 = packf2(a[i], a[i]);
#pragma unroll
                for (int j = 0; j < 4; j++) acc[i][j] = ffma2(a2, b2[j], acc[i][j]);
            }
        }
    }

    // store (f32x2 pair = 8-byte aligned store; pairs never straddle N_TRAIN
    // since N_TRAIN is even and n is even)
#pragma unroll
    for (int i = 0; i < 8; i++) {
        float* orow = g_sim + (size_t)(m_base + m0 + i) * N_TRAIN;
#pragma unroll
        for (int j = 0; j < 4; j++) {
            int n = n_base + n0 + 2 * j;
            if (n < N_TRAIN) *(u64*)(orow + n) = acc[i][j];
        }
    }
}

// ---------------------------------------------------------------------------
// Per-row top-200 + softmax + cumulative class histograms. One block per row.
// ---------------------------------------------------------------------------
__device__ __forceinline__ u32 enc_key(float f) {
    u32 u = __float_as_uint(f);
    return (u & 0x80000000u) ? ~u : (u | 0x80000000u);
}
__device__ __forceinline__ float dec_key(u32 u) {
    return (u & 0x80000000u) ? __uint_as_float(u & 0x7FFFFFFFu)
                             : __uint_as_float(~u);
}

// descending bitonic sort of n (power of 2) u64 entries, 256 threads
__device__ void bitonic_desc(u64* a, int n, int tid) {
    for (int k = 2; k <= n; k <<= 1) {
        for (int j = k >> 1; j > 0; j >>= 1) {
            for (int i = tid; i < n; i += 256) {
                int ixj = i ^ j;
                if (ixj > i) {
                    u64 x = a[i], y = a[ixj];
                    bool desc = ((i & k) == 0);
                    if (desc ? (x < y) : (x > y)) { a[i] = y; a[ixj] = x; }
                }
            }
            __syncthreads();
        }
    }
}

__global__ __launch_bounds__(256) void select_kernel(
    const int* __restrict__ labels, float* __restrict__ out)
{
    __shared__ u64 buf[CAP];        // 32 KB: samples, then candidates
    __shared__ float hist[NCLS];
    __shared__ float tw[MAXK];
    __shared__ int   tl[MAXK];
    __shared__ float red[256];
    __shared__ u32 s_cnt;
    __shared__ u32 s_thr;

    const int tid = threadIdx.x;
    const int row = blockIdx.x;
    const float* sim = g_sim + (size_t)row * N_TRAIN;

    // --- 1) sample 4096 elements (stride 24), sort, threshold = rank-64 key.
    // Expected candidate count ~(64/4096)*100000 = 1562; P(<200) and P(>4096)
    // are both many sigma out.
    for (int i = tid; i < CAP; i += 256)
        buf[i] = ((u64)enc_key(sim[i * 24]) << 32);
    if (tid == 0) s_cnt = 0;
    __syncthreads();
    bitonic_desc(buf, CAP, tid);
    if (tid == 0) s_thr = (u32)(buf[63] >> 32);
    __syncthreads();
    const u32 thr = s_thr;

    // --- 2) collect all elements with key >= thr (vectorized scan)
    const float4* sim4 = (const float4*)sim;
    for (int i = tid; i < N_TRAIN / 4; i += 256) {
        float4 v = sim4[i];
        float c[4] = {v.x, v.y, v.z, v.w};
#pragma unroll
        for (int q = 0; q < 4; q++) {
            u32 key = enc_key(c[q]);
            if (key >= thr) {
                u32 p = atomicAdd(&s_cnt, 1u);
                // key desc, then index asc on ties (matches top_k tie-break)
                if (p < CAP) buf[p] = ((u64)key << 32) | (u32)(~(u32)(4 * i + q));
            }
        }
    }
    __syncthreads();
    int C = min((int)s_cnt, CAP);
    int np2 = 256;
    while (np2 < C) np2 <<= 1;
    for (int i = C + tid; i < np2; i += 256) buf[i] = 0ULL;
    __syncthreads();
    bitonic_desc(buf, np2, tid);

    // --- 3) softmax over the sorted top-200
    float smax = dec_key((u32)(buf[0] >> 32));
    float w = 0.0f;
    int lab = 0;
    if (tid < MAXK && tid < C) {
        u64 e = buf[tid];
        float s = dec_key((u32)(e >> 32));
        u32 idx = ~(u32)e;
        w = __expf((s - smax) * TINV);
        lab = labels[idx];
    }
    red[tid] = w;
    __syncthreads();
    for (int off = 128; off > 0; off >>= 1) {
        if (tid < off) red[tid] += red[tid + off];
        __syncthreads();
    }
    const float wsum = red[0];
    if (tid < MAXK) { tw[tid] = w / wsum; tl[tid] = lab; }

    // --- 4) cumulative class histograms for k = 10, 20, 100, 200
    for (int c = tid; c < NCLS; c += 256) hist[c] = 0.0f;
    __syncthreads();
    const int seg_lo[4] = {0, 10, 20, 100};
    const int seg_hi[4] = {10, 20, 100, 200};
    for (int ks = 0; ks < 4; ks++) {
        if (tid >= seg_lo[ks] && tid < seg_hi[ks])
            atomicAdd(&hist[tl[tid]], tw[tid]);
        __syncthreads();
        float* o = out + ((size_t)ks * B_ROWS + row) * NCLS;
        for (int c = tid; c < NCLS; c += 256) o[c] = hist[c];
        __syncthreads();
    }
}

// ---------------------------------------------------------------------------
extern "C" void kernel_launch(void* const* d_in, const int* in_sizes, int n_in,
                              void* d_out, int out_size)
{
    const float* feats  = (const float*)d_in[0];  // [2048, 1024]
    const float* train  = (const float*)d_in[1];  // [100000, 1024]
    const int*   labels = (const int*)d_in[2];    // [100000]
    float* out = (float*)d_out;                   // 4 x [2048, 1000]

    dim3 grid((N_TRAIN + BN - 1) / BN, B_ROWS / BM);
    gemm_kernel<<<grid, 256>>>(feats, train);
    select_kernel<<<B_ROWS, 256>>>(labels, out);
}

// round 6
// speedup vs baseline: 5.9547x; 5.9547x over previous
#include <cuda_runtime.h>
#include <cuda_bf16.h>
#include <cstdint>

typedef unsigned long long u64;
typedef unsigned int u32;
typedef unsigned short u16;

#define B_ROWS 2048
#define N_TRAIN 100000
#define KDIM 1024
#define NCLS 1000
#define MAXK 200
#define CCAP 1024
#define TINV (1.0f / 0.07f)

// device scratch (allocation-free)
__device__ __nv_bfloat16 g_fb[(size_t)B_ROWS * KDIM];     // 4 MB
__device__ __nv_bfloat16 g_tb[(size_t)N_TRAIN * KDIM];    // 205 MB
__device__ u16 g_simb[(size_t)B_ROWS * N_TRAIN];          // 410 MB (bf16 bits)
__device__ int g_cand[(size_t)B_ROWS * CCAP];
__device__ int g_cnt[B_ROWS];

// ---------------------------------------------------------------- helpers
__device__ __forceinline__ u32 smem_u32(const void* p) {
    u32 a;
    asm("{ .reg .u64 t; cvta.to.shared.u64 t, %1; cvt.u32.u64 %0, t; }"
        : "=r"(a) : "l"(p));
    return a;
}
#define SWZ(x) ((x) ^ (((x) >> 3) & 0x70))

// 16-bit order keys over bf16 bit patterns
__device__ __forceinline__ u32 enc16(u32 x) {
    return (x & 0x8000u) ? ((~x) & 0xFFFFu) : (x | 0x8000u);
}
__device__ __forceinline__ float dec16(u32 k) {
    u32 b = (k & 0x8000u) ? (k & 0x7FFFu) : ((~k) & 0xFFFFu);
    return __uint_as_float(b << 16);
}
__device__ __forceinline__ u32 enc32(float f) {
    u32 u = __float_as_uint(f);
    return (u & 0x80000000u) ? ~u : (u | 0x80000000u);
}
__device__ __forceinline__ float dec32(u32 u) {
    return (u & 0x80000000u) ? __uint_as_float(u & 0x7FFFFFFFu)
                             : __uint_as_float(~u);
}

__device__ __forceinline__ void cp16(u32 dst, const void* src) {
    asm volatile("cp.async.cg.shared.global [%0], [%1], 16;"
                 :: "r"(dst), "l"(src) : "memory");
}
__device__ __forceinline__ void ldmx4(u32* r, u32 addr) {
    asm volatile("ldmatrix.sync.aligned.m8n8.x4.shared.b16 {%0,%1,%2,%3},[%4];"
                 : "=r"(r[0]), "=r"(r[1]), "=r"(r[2]), "=r"(r[3]) : "r"(addr));
}
__device__ __forceinline__ void mma16816(float* d, const u32* a, const u32* b) {
    asm volatile(
        "mma.sync.aligned.m16n8k16.row.col.f32.bf16.bf16.f32 "
        "{%0,%1,%2,%3},{%4,%5,%6,%7},{%8,%9},{%0,%1,%2,%3};"
        : "+f"(d[0]), "+f"(d[1]), "+f"(d[2]), "+f"(d[3])
        : "r"(a[0]), "r"(a[1]), "r"(a[2]), "r"(a[3]), "r"(b[0]), "r"(b[1]));
}

// ---------------------------------------------------------- fp32 -> bf16
__global__ __launch_bounds__(256) void conv_kernel(const float* __restrict__ src,
                                                   __nv_bfloat16* dst, int n4) {
    for (int i = blockIdx.x * 256 + threadIdx.x; i < n4; i += gridDim.x * 256) {
        float4 v = ((const float4*)src)[i];
        u32 lo, hi;
        asm("cvt.rn.bf16x2.f32 %0, %1, %2;" : "=r"(lo) : "f"(v.y), "f"(v.x));
        asm("cvt.rn.bf16x2.f32 %0, %1, %2;" : "=r"(hi) : "f"(v.w), "f"(v.z));
        ((uint2*)dst)[i] = make_uint2(lo, hi);
    }
}

// ------------------------------------------------- HMMA bf16 GEMM
// sim[m][n] ~= sum_d feats[m][d]*train[n][d].  CTA tile 128x128, BK=64,
// 8 warps (2x4), warp tile 64x32, 3-stage cp.async pipeline, SW128 smem.
#define GM 128
#define GN 128
#define GK 64
#define STAGE_B (GM * GK * 2 + GN * GK * 2)   // 32768
#define NSTAGE 3
#define NK (KDIM / GK)                        // 16
#define GEMM_SMEM (NSTAGE * STAGE_B)          // 98304

__device__ __forceinline__ void issue_tile(u32 sbase, int tid, int m_base,
                                           int n_base, int kt) {
    // A: 128 rows x 128B (1024 chunks of 16B); B same. 4+4 chunks/thread.
#pragma unroll
    for (int q = 0; q < 4; q++) {
        int idx = tid + q * 256;
        int r = idx >> 3, c = idx & 7;   // c: 16B chunk = 8 bf16
        const void* src = g_fb + ((size_t)(m_base + r) << 10) + kt + c * 8;
        cp16(sbase + SWZ(r * 128 + c * 16), src);
    }
    u32 bbase = sbase + GM * GK * 2;
#pragma unroll
    for (int q = 0; q < 4; q++) {
        int idx = tid + q * 256;
        int r = idx >> 3, c = idx & 7;
        int n = n_base + r;
        if (n >= N_TRAIN) n = N_TRAIN - 1;   // clamp: finite garbage, never stored
        const void* src = g_tb + ((size_t)n << 10) + kt + c * 8;
        cp16(bbase + SWZ(r * 128 + c * 16), src);
    }
    asm volatile("cp.async.commit_group;" ::: "memory");
}

__global__ __launch_bounds__(256) void gemm_hmma() {
    extern __shared__ char dsm[];
    const u32 sb = smem_u32(dsm);
    const int tid = threadIdx.x;
    const int wid = tid >> 5, lane = tid & 31;
    const int m_base = blockIdx.x * GM;
    const int n_base = blockIdx.y * GN;

    const int warp_m = wid >> 2;             // 0..1 -> m offset 64
    const int warp_n = wid & 3;              // 0..3 -> n offset 32
    const int wm0 = warp_m * 64, wn0 = warp_n * 32;

    float acc[4][4][4];
#pragma unroll
    for (int i = 0; i < 4; i++)
#pragma unroll
        for (int j = 0; j < 4; j++)
#pragma unroll
            for (int q = 0; q < 4; q++) acc[i][j][q] = 0.0f;

    // preload stages 0,1
    issue_tile(sb, tid, m_base, n_base, 0);
    issue_tile(sb + STAGE_B, tid, m_base, n_base, GK);

    // ldmatrix address components (within a stage)
    const int a_row_sel = lane & 15;         // row within 16
    const int a_kh = (lane >> 4) & 1;        // k half (8)
    const int b_n_sel = (lane & 7) + ((lane & 16) >> 1);  // 0..15
    const int b_kh = (lane >> 3) & 1;

    for (int kt = 0; kt < NK; kt++) {
        asm volatile("cp.async.wait_group 1;" ::: "memory");
        __syncthreads();
        if (kt + 2 < NK)
            issue_tile(sb + ((kt + 2) % NSTAGE) * STAGE_B, tid, m_base, n_base,
                       (kt + 2) * GK);

        const u32 abase = sb + (kt % NSTAGE) * STAGE_B;
        const u32 bbase = abase + GM * GK * 2;
#pragma unroll
        for (int ks = 0; ks < 4; ks++) {
            u32 afrag[4][4], bfrag[2][4];
#pragma unroll
            for (int mi = 0; mi < 4; mi++) {
                int row = wm0 + mi * 16 + a_row_sel;
                int col = ks * 16 + a_kh * 8;
                ldmx4(afrag[mi], abase + SWZ(row * 128 + col * 2));
            }
#pragma unroll
            for (int p = 0; p < 2; p++) {
                int row = wn0 + p * 16 + b_n_sel;
                int col = ks * 16 + b_kh * 8;
                ldmx4(bfrag[p], bbase + SWZ(row * 128 + col * 2));
            }
#pragma unroll
            for (int mi = 0; mi < 4; mi++)
#pragma unroll
                for (int nj = 0; nj < 4; nj++)
                    mma16816(acc[mi][nj], afrag[mi], &bfrag[nj >> 1][(nj & 1) * 2]);
        }
    }
    asm volatile("cp.async.wait_group 0;" ::: "memory");
    __syncthreads();

    // epilogue: acc -> bf16x2 in smem [128][68 u32], then coalesced stores
    u32* ep = (u32*)dsm;
    const int tg = lane >> 2;      // 0..7 (row within 8)
    const int tc = lane & 3;       // col pair
#pragma unroll
    for (int mi = 0; mi < 4; mi++) {
#pragma unroll
        for (int nj = 0; nj < 4; nj++) {
            u32 p0, p1;
            asm("cvt.rn.bf16x2.f32 %0, %1, %2;"
                : "=r"(p0) : "f"(acc[mi][nj][1]), "f"(acc[mi][nj][0]));
            asm("cvt.rn.bf16x2.f32 %0, %1, %2;"
                : "=r"(p1) : "f"(acc[mi][nj][3]), "f"(acc[mi][nj][2]));
            int r0 = wm0 + mi * 16 + tg;
            int cu = (wn0 + nj * 8) / 2 + tc;
            ep[r0 * 68 + cu] = p0;
            ep[(r0 + 8) * 68 + cu] = p1;
        }
    }
    __syncthreads();
#pragma unroll
    for (int it = 0; it < 8; it++) {
        int idx = tid + it * 256;
        int r = idx >> 4, c4 = idx & 15;          // c4: uint4 chunk (8 n)
        int n = n_base + c4 * 8;
        if (n < N_TRAIN) {
            uint4 v = *(uint4*)(ep + r * 68 + c4 * 4);
            *(uint4*)(g_simb + (size_t)(m_base + r) * N_TRAIN + n) = v;
        }
    }
}

// ---------------------------------------------- selection A: threshold+collect
__global__ __launch_bounds__(256) void selA_kernel() {
    __shared__ u32 h8[8][256];
    __shared__ u32 hist[256];
    __shared__ int s_bstar, s_above;
    __shared__ u32 s_k200, s_cnt;

    const int tid = threadIdx.x;
    const int wid = tid >> 5;
    const int row = blockIdx.x;
    const uint4* srow = (const uint4*)(g_simb + (size_t)row * N_TRAIN);

    for (int i = tid; i < 2048; i += 256) ((u32*)h8)[i] = 0;
    if (tid == 0) s_cnt = 0;
    __syncthreads();
    // pass 1: hi-byte histogram
    for (int i = tid; i < N_TRAIN / 8; i += 256) {
        uint4 v = srow[i];
        u32 w[4] = {v.x, v.y, v.z, v.w};
#pragma unroll
        for (int j = 0; j < 4; j++) {
            atomicAdd(&h8[wid][enc16(w[j] & 0xFFFFu) >> 8], 1u);
            atomicAdd(&h8[wid][enc16(w[j] >> 16) >> 8], 1u);
        }
    }
    __syncthreads();
    if (tid < 256) {
        u32 s = 0;
#pragma unroll
        for (int w = 0; w < 8; w++) s += h8[w][tid];
        hist[tid] = s;
    }
    __syncthreads();
    if (tid == 0) {
        int cum = 0, b = 255;
        for (; b > 0; b--) {
            cum += (int)hist[b];
            if (cum >= MAXK) break;
        }
        s_bstar = b;
        s_above = cum - (int)hist[b];
    }
    __syncthreads();
    const u32 bstar = (u32)s_bstar;
    for (int i = tid; i < 2048; i += 256) ((u32*)h8)[i] = 0;
    __syncthreads();
    // pass 2: lo-byte histogram within bin bstar
    for (int i = tid; i < N_TRAIN / 8; i += 256) {
        uint4 v = srow[i];
        u32 w[4] = {v.x, v.y, v.z, v.w};
#pragma unroll
        for (int j = 0; j < 4; j++) {
            u32 k0 = enc16(w[j] & 0xFFFFu), k1 = enc16(w[j] >> 16);
            if ((k0 >> 8) == bstar) atomicAdd(&h8[wid][k0 & 255u], 1u);
            if ((k1 >> 8) == bstar) atomicAdd(&h8[wid][k1 & 255u], 1u);
        }
    }
    __syncthreads();
    if (tid < 256) {
        u32 s = 0;
#pragma unroll
        for (int w = 0; w < 8; w++) s += h8[w][tid];
        hist[tid] = s;
    }
    __syncthreads();
    if (tid == 0) {
        int cum = s_above, l = 255;
        for (; l > 0; l--) {
            cum += (int)hist[l];
            if (cum >= MAXK) break;
        }
        u32 k200 = (bstar << 8) | (u32)l;         // approx rank-200 key
        float vt = dec16(k200) - 3.0f;            // margin >= 2x error bound
        __nv_bfloat16 hb = __float2bfloat16_rd(vt);
        s_k200 = enc16((u32)__bfloat16_as_ushort(hb));
    }
    __syncthreads();
    const u32 thr = s_k200;
    // pass 3: collect candidate indices
    for (int i = tid; i < N_TRAIN / 8; i += 256) {
        uint4 v = srow[i];
        u32 w[4] = {v.x, v.y, v.z, v.w};
#pragma unroll
        for (int j = 0; j < 4; j++) {
#pragma unroll
            for (int h = 0; h < 2; h++) {
                u32 k = enc16(h ? (w[j] >> 16) : (w[j] & 0xFFFFu));
                if (k >= thr) {
                    u32 p = atomicAdd(&s_cnt, 1u);
                    if (p < CCAP) g_cand[(size_t)row * CCAP + p] = i * 8 + j * 2 + h;
                }
            }
        }
    }
    __syncthreads();
    if (tid == 0) g_cnt[row] = min((int)s_cnt, CCAP);
}

// -------------------------- selection B: exact rescore + sort + softmax + out
__global__ __launch_bounds__(256) void selB_kernel(
    const float* __restrict__ feats, const float* __restrict__ train,
    const int* __restrict__ labels, float* __restrict__ out) {
    __shared__ float4 fsh[256];
    __shared__ u64 buf[CCAP];
    __shared__ float hist[NCLS];
    __shared__ float tw[MAXK];
    __shared__ int tl[MAXK];
    __shared__ float red[256];

    const int tid = threadIdx.x;
    const int wid = tid >> 5, lid = tid & 31;
    const int row = blockIdx.x;

    fsh[tid] = ((const float4*)(feats + (size_t)row * KDIM))[tid];
    __syncthreads();
    const int C = g_cnt[row];

    for (int base = 0; base < C; base += 8) {
        int ci = base + wid;
        if (ci < C) {
            int idx = g_cand[(size_t)row * CCAP + ci];
            const float4* tr = (const float4*)(train + (size_t)idx * KDIM);
            float s = 0.0f;
#pragma unroll
            for (int j = 0; j < 8; j++) {
                float4 t = tr[j * 32 + lid];
                float4 f = fsh[j * 32 + lid];
                s += t.x * f.x + t.y * f.y + t.z * f.z + t.w * f.w;
            }
#pragma unroll
            for (int o = 16; o > 0; o >>= 1) s += __shfl_xor_sync(~0u, s, o);
            if (lid == 0)
                buf[ci] = ((u64)enc32(s) << 32) | (u32)(~(u32)idx);
        }
    }
    __syncthreads();
    int np2 = 256;
    while (np2 < C) np2 <<= 1;
    for (int i = C + tid; i < np2; i += 256) buf[i] = 0ULL;
    __syncthreads();
    // descending bitonic sort (key desc, index asc on ties via ~idx)
    for (int k = 2; k <= np2; k <<= 1)
        for (int j = k >> 1; j > 0; j >>= 1) {
            for (int i = tid; i < np2; i += 256) {
                int ixj = i ^ j;
                if (ixj > i) {
                    u64 x = buf[i], y = buf[ixj];
                    bool desc = ((i & k) == 0);
                    if (desc ? (x < y) : (x > y)) { buf[i] = y; buf[ixj] = x; }
                }
            }
            __syncthreads();
        }
    // softmax over exact top-200
    float smax = dec32((u32)(buf[0] >> 32));
    float w = 0.0f;
    int lab = 0;
    if (tid < MAXK && tid < C) {
        u64 e = buf[tid];
        w = __expf((dec32((u32)(e >> 32)) - smax) * TINV);
        lab = labels[~(u32)e];
    }
    red[tid] = w;
    __syncthreads();
    for (int off = 128; off > 0; off >>= 1) {
        if (tid < off) red[tid] += red[tid + off];
        __syncthreads();
    }
    const float wsum = red[0];
    if (tid < MAXK) { tw[tid] = w / wsum; tl[tid] = lab; }
    for (int c = tid; c < NCLS; c += 256) hist[c] = 0.0f;
    __syncthreads();
    const int seg_lo[4] = {0, 10, 20, 100};
    const int seg_hi[4] = {10, 20, 100, 200};
    for (int ks = 0; ks < 4; ks++) {
        if (tid >= seg_lo[ks] && tid < seg_hi[ks])
            atomicAdd(&hist[tl[tid]], tw[tid]);
        __syncthreads();
        float* o = out + ((size_t)ks * B_ROWS + row) * NCLS;
        for (int c = tid; c < NCLS; c += 256) o[c] = hist[c];
        __syncthreads();
    }
}

// ---------------------------------------------------------------------------
extern "C" void kernel_launch(void* const* d_in, const int* in_sizes, int n_in,
                              void* d_out, int out_size) {
    const float* feats = (const float*)d_in[0];
    const float* train = (const float*)d_in[1];
    const int* labels = (const int*)d_in[2];
    float* out = (float*)d_out;

    static int inited = 0;
    if (!inited) {
        cudaFuncSetAttribute(gemm_hmma,
                             cudaFuncAttributeMaxDynamicSharedMemorySize,
                             GEMM_SMEM);
        inited = 1;
    }

    __nv_bfloat16* fb;
    __nv_bfloat16* tb;
    cudaGetSymbolAddress((void**)&fb, g_fb);
    cudaGetSymbolAddress((void**)&tb, g_tb);

    conv_kernel<<<256, 256>>>(feats, fb, B_ROWS * KDIM / 4);
    conv_kernel<<<2048, 256>>>(train, tb, N_TRAIN * KDIM / 4);

    dim3 grid_g(B_ROWS / GM, (N_TRAIN + GN - 1) / GN);
    gemm_hmma<<<grid_g, 256, GEMM_SMEM>>>();

    selA_kernel<<<B_ROWS, 256>>>();
    selB_kernel<<<B_ROWS, 256>>>(feats, train, labels, out);
}